// round 15
// baseline (speedup 1.0000x reference)
#include <cuda_runtime.h>
#include <cuda_fp16.h>
#include <math.h>
#include <stdint.h>

#define BB 4
#define CC 128
#define NPIX 4096
#define NH 4
#define DH 32
#define EPSF 1e-6f
// (1/sqrt(32)) * log2(e)
#define SCALE2 0.25503486f

// Scratch (device globals)
__device__ __half g_ht[(size_t)BB * NPIX * CC];        // normed h fp16 [b][n][c]
__device__ __half g_wq[384 * 128];                     // qkv_w plain fp16
__device__ __half g_wp[128 * 128];                     // proj_w plain fp16
__device__ __half g_q16[(size_t)BB * NH * NPIX * DH];  // [bh][n][c], scaled
__device__ __half g_k16[(size_t)BB * NH * NPIX * DH];  // [bh][n][c]
__device__ __half g_v16[(size_t)BB * NH * DH * NPIX];  // [bh][c][n]
__device__ __half g_at[(size_t)BB * NPIX * CC];        // attn out fp16 [b][n][c]
__device__ float  g_qb[BB * NH * NPIX];                // |q_n| per row
__device__ unsigned g_kmax[BB * NH];                   // bits of max |k|^2

// ---------------------------------------------------------------------------
// helpers
// ---------------------------------------------------------------------------
__device__ __forceinline__ uint32_t hex2(uint32_t a) {
    uint32_t d;
    asm("ex2.approx.f16x2 %0, %1;" : "=r"(d) : "r"(a));
    return d;
}

__device__ __forceinline__ uint32_t hadd2(uint32_t a, uint32_t b) {
    uint32_t d;
    asm("add.f16x2 %0, %1, %2;" : "=r"(d) : "r"(a), "r"(b));
    return d;
}

__device__ __forceinline__ uint32_t hsub2(uint32_t a, uint32_t b) {
    uint32_t d;
    asm("sub.f16x2 %0, %1, %2;" : "=r"(d) : "r"(a), "r"(b));
    return d;
}

__device__ __forceinline__ void mma16816h(float* d, const uint32_t* a,
                                          const uint32_t* b) {
    asm volatile(
        "mma.sync.aligned.m16n8k16.row.col.f32.f16.f16.f32 "
        "{%0,%1,%2,%3},{%4,%5,%6,%7},{%8,%9},{%0,%1,%2,%3};"
        : "+f"(d[0]), "+f"(d[1]), "+f"(d[2]), "+f"(d[3])
        : "r"(a[0]), "r"(a[1]), "r"(a[2]), "r"(a[3]), "r"(b[0]), "r"(b[1]));
}

__device__ __forceinline__ void ldmx4(uint32_t& r0, uint32_t& r1, uint32_t& r2,
                                      uint32_t& r3, uint32_t addr) {
    asm volatile(
        "ldmatrix.sync.aligned.m8n8.x4.shared.b16 {%0,%1,%2,%3}, [%4];"
        : "=r"(r0), "=r"(r1), "=r"(r2), "=r"(r3) : "r"(addr));
}

__device__ __forceinline__ uint32_t pack_f16x2(float a, float b) {
    uint32_t r;
    asm("cvt.rn.f16x2.f32 %0, %1, %2;" : "=r"(r) : "f"(b), "f"(a));
    return r;
}

__device__ __forceinline__ void cpasync16(uint32_t s, const void* g) {
    asm volatile("cp.async.cg.shared.global [%0], [%1], 16;"
                 :: "r"(s), "l"(g) : "memory");
}
#define CP_COMMIT() asm volatile("cp.async.commit_group;" ::: "memory")

// ---------------------------------------------------------------------------
// K0: weight conversion (both plain fp16) + g_kmax reset
// ---------------------------------------------------------------------------
__global__ void wconv_kernel(const float* __restrict__ qkv_w,
                             const float* __restrict__ proj_w) {
    int t = blockIdx.x * 256 + threadIdx.x;   // 0 .. 65535
    if (t < BB * NH) g_kmax[t] = 0u;
    if (t < 384 * 128) {
        g_wq[t] = __float2half_rn(qkv_w[t]);
    } else {
        int idx = t - 384 * 128;
        g_wp[idx] = __float2half_rn(proj_w[idx]);
    }
}

// ---------------------------------------------------------------------------
// K1: LayerNorm, 4 threads/pixel -> fp16 [b][n][c]. 256 CTAs.
// ---------------------------------------------------------------------------
__global__ void __launch_bounds__(256) norm_kernel(
    const float* __restrict__ x, const float* __restrict__ w,
    const float* __restrict__ bias) {
    __shared__ float sred[2][4][64];
    const int tid = threadIdx.x;
    const int n_loc = tid & 63;
    const int cg = tid >> 6;
    const int pix = blockIdx.x * 64 + n_loc;
    const int b = pix >> 12, n = pix & (NPIX - 1);
    const float* xp = x + (size_t)b * CC * NPIX + n;

    float vals[32];
    float s = 0.f, s2 = 0.f;
#pragma unroll
    for (int i = 0; i < 32; i++) {
        float v = xp[(size_t)(cg * 32 + i) * NPIX];
        vals[i] = v;
        s += v;
        s2 = fmaf(v, v, s2);
    }
    sred[0][cg][n_loc] = s;
    sred[1][cg][n_loc] = s2;
    __syncthreads();
    s  = sred[0][0][n_loc] + sred[0][1][n_loc] + sred[0][2][n_loc] + sred[0][3][n_loc];
    s2 = sred[1][0][n_loc] + sred[1][1][n_loc] + sred[1][2][n_loc] + sred[1][3][n_loc];
    float mean = s * (1.0f / CC);
    float var  = s2 * (1.0f / CC) - mean * mean;
    float inv  = rsqrtf(var + EPSF);

    __half* hp = g_ht + ((size_t)b * NPIX + n) * CC + cg * 32;
#pragma unroll
    for (int i = 0; i < 32; i += 2) {
        int c = cg * 32 + i;
        float v0 = (vals[i] - mean) * inv * w[c] + bias[c];
        float v1 = (vals[i + 1] - mean) * inv * w[c + 1] + bias[c + 1];
        *(__half2*)(hp + i) = __floats2half2_rn(v0, v1);
    }
}

// ---------------------------------------------------------------------------
// K2: qkv GEMM (plain fp16 weights) + fused layouts + stats.
// ---------------------------------------------------------------------------
__global__ void __launch_bounds__(256) gemmqkv_kernel(
    const float* __restrict__ bias) {
    __shared__ __align__(16) __half Hs[128][136];
    __shared__ float red[8];

    const int tid = threadIdx.x, lane = tid & 31, wid = tid >> 5;
    const int g = lane >> 2, qu = (lane & 3) * 2;
    const int b = blockIdx.z, o0 = blockIdx.y * 64, n0 = blockIdx.x * 128;
    const int os = wid & 3, ns = wid >> 2;

    {
        const __half* hsrc = g_ht + ((size_t)b * NPIX + n0) * CC;
        int row = tid >> 1, part = tid & 1;
#pragma unroll
        for (int j = 0; j < 8; j++)
            *(uint4*)&Hs[row][part * 64 + j * 8] =
                *(const uint4*)(hsrc + (size_t)row * CC + part * 64 + j * 8);
    }
    __syncthreads();

    float acc[8][4];
#pragma unroll
    for (int nj = 0; nj < 8; nj++)
#pragma unroll
        for (int r = 0; r < 4; r++) acc[nj][r] = 0.f;

    const __half* w0 = g_wq + (size_t)(o0 + os * 16 + g) * 128;
    const __half* w8 = w0 + 8 * 128;

#pragma unroll
    for (int kk = 0; kk < 8; kk++) {
        int c0 = kk * 16 + qu;
        uint32_t ah[4];
        ah[0] = *(const uint32_t*)(w0 + c0);
        ah[1] = *(const uint32_t*)(w8 + c0);
        ah[2] = *(const uint32_t*)(w0 + c0 + 8);
        ah[3] = *(const uint32_t*)(w8 + c0 + 8);
#pragma unroll
        for (int nj = 0; nj < 8; nj++) {
            uint32_t bf[2];
            const __half* hrow = &Hs[ns * 64 + nj * 8 + g][0];
            bf[0] = *(const uint32_t*)(hrow + c0);
            bf[1] = *(const uint32_t*)(hrow + c0 + 8);
            mma16816h(acc[nj], ah, bf);
        }
    }

    const int orow = o0 + os * 16 + g;
    const float b0 = bias[orow], b8 = bias[orow + 8];

    if (o0 >= 256) {
        int h = (orow - 256) >> 5, c = orow & 31;
        __half* v0p = g_v16 + ((size_t)(b * NH + h) * DH + c) * NPIX + n0;
        __half* v8p = v0p + 8 * NPIX;
#pragma unroll
        for (int nj = 0; nj < 8; nj++) {
            int n = ns * 64 + nj * 8 + qu;
            *(__half2*)(v0p + n) = __floats2half2_rn(acc[nj][0] + b0, acc[nj][1] + b0);
            *(__half2*)(v8p + n) = __floats2half2_rn(acc[nj][2] + b8, acc[nj][3] + b8);
        }
    } else {
        const bool isQ = (o0 < 128);
        const float sc = isQ ? SCALE2 : 1.0f;
        __syncthreads();
        int lo = os * 16 + g;
#pragma unroll
        for (int nj = 0; nj < 8; nj++) {
            int nn = ns * 64 + nj * 8 + qu;
            *(__half2*)&Hs[lo][nn] =
                __floats2half2_rn((acc[nj][0] + b0) * sc, (acc[nj][1] + b0) * sc);
            *(__half2*)&Hs[lo + 8][nn] =
                __floats2half2_rn((acc[nj][2] + b8) * sc, (acc[nj][3] + b8) * sc);
        }
        __syncthreads();
        int n_loc = tid & 127;
        int hseg = tid >> 7;
        int oBase = (isQ ? o0 : o0 - 128) + hseg * 32;
        int head = oBase >> 5;
        int bh = b * NH + head;
        __half* dst = (isQ ? g_q16 : g_k16) +
                      ((size_t)bh * NPIX + n0 + n_loc) * DH;
        __half tmp[32];
        float nrm2 = 0.f;
#pragma unroll
        for (int c = 0; c < 32; c++) {
            tmp[c] = Hs[hseg * 32 + c][n_loc];
            float f = __half2float(tmp[c]);
            nrm2 = fmaf(f, f, nrm2);
        }
#pragma unroll
        for (int j = 0; j < 4; j++)
            *(uint4*)(dst + j * 8) = *(uint4*)(tmp + j * 8);

        if (isQ) {
            g_qb[(size_t)bh * NPIX + n0 + n_loc] = sqrtf(nrm2);
        } else {
#pragma unroll
            for (int off = 16; off > 0; off >>= 1)
                nrm2 = fmaxf(nrm2, __shfl_xor_sync(0xffffffffu, nrm2, off));
            if (lane == 0) red[wid] = nrm2;
            __syncthreads();
            if ((tid & 127) == 0) {
                float m = fmaxf(fmaxf(red[hseg * 4], red[hseg * 4 + 1]),
                                fmaxf(red[hseg * 4 + 2], red[hseg * 4 + 3]));
                atomicMax(&g_kmax[bh], __float_as_uint(m));
            }
        }
    }
}

// ---------------------------------------------------------------------------
// K4: proj GEMM (plain fp16 weights): fp32 out + bias + residual
// ---------------------------------------------------------------------------
__global__ void __launch_bounds__(256) gemm16_kernel(
    const __half* __restrict__ W2, const float* __restrict__ bias,
    const __half* __restrict__ Hin, float* __restrict__ Out,
    const float* __restrict__ resid, int Otot) {
    __shared__ __align__(16) __half Hs[128][136];

    const int tid = threadIdx.x, lane = tid & 31, wid = tid >> 5;
    const int g = lane >> 2, qu = (lane & 3) * 2;
    const int b = blockIdx.z, o0 = blockIdx.y * 64, n0 = blockIdx.x * 128;
    const int os = wid & 3, ns = wid >> 2;

    {
        const __half* hsrc = Hin + ((size_t)b * NPIX + n0) * CC;
        int row = tid >> 1, part = tid & 1;
#pragma unroll
        for (int j = 0; j < 8; j++)
            *(uint4*)&Hs[row][part * 64 + j * 8] =
                *(const uint4*)(hsrc + (size_t)row * CC + part * 64 + j * 8);
    }
    __syncthreads();

    float acc[8][4];
#pragma unroll
    for (int nj = 0; nj < 8; nj++)
#pragma unroll
        for (int r = 0; r < 4; r++) acc[nj][r] = 0.f;

    const __half* w0 = W2 + (size_t)(o0 + os * 16 + g) * 128;
    const __half* w8 = w0 + 8 * 128;

#pragma unroll
    for (int kk = 0; kk < 8; kk++) {
        int c0 = kk * 16 + qu;
        uint32_t ah[4];
        ah[0] = *(const uint32_t*)(w0 + c0);
        ah[1] = *(const uint32_t*)(w8 + c0);
        ah[2] = *(const uint32_t*)(w0 + c0 + 8);
        ah[3] = *(const uint32_t*)(w8 + c0 + 8);
#pragma unroll
        for (int nj = 0; nj < 8; nj++) {
            uint32_t bf[2];
            const __half* hrow = &Hs[ns * 64 + nj * 8 + g][0];
            bf[0] = *(const uint32_t*)(hrow + c0);
            bf[1] = *(const uint32_t*)(hrow + c0 + 8);
            mma16816h(acc[nj], ah, bf);
        }
    }

    const int orow = o0 + os * 16 + g;
    const float b0 = bias[orow], b8 = bias[orow + 8];
#pragma unroll
    for (int nj = 0; nj < 8; nj++) {
        int n = n0 + ns * 64 + nj * 8 + qu;
        float2 v0 = make_float2(acc[nj][0] + b0, acc[nj][1] + b0);
        float2 v1 = make_float2(acc[nj][2] + b8, acc[nj][3] + b8);
        float2 r0 = *(const float2*)(resid + ((size_t)b * Otot + orow) * NPIX + n);
        float2 r1 = *(const float2*)(resid + ((size_t)b * Otot + orow + 8) * NPIX + n);
        v0.x += r0.x; v0.y += r0.y;
        v1.x += r1.x; v1.y += r1.y;
        *(float2*)(Out + ((size_t)b * Otot + orow) * NPIX + n) = v0;
        *(float2*)(Out + ((size_t)b * Otot + orow + 8) * NPIX + n) = v1;
    }
}

// ---------------------------------------------------------------------------
// K3: flash attention, softmax-bound, 4-stage cp.async pipeline.
// CTA = 256 thr (8 warps), warp = 32 q rows (2 mi tiles) -> 256 q per CTA.
// Chunk body order: QK -> P -> PV MMAs -> row sums (off the tensor path).
// ---------------------------------------------------------------------------
#define KBUF (64 * 40 * 2)
#define VBUF (32 * 72 * 2)
__global__ void __launch_bounds__(256, 2) attn_mma_kernel() {
    __shared__ __align__(16) __half Ks[4][64][40];
    __shared__ __align__(16) __half Vs[4][32][72];

    const int tid = threadIdx.x;
    const int lane = tid & 31;
    const int wid = tid >> 5;
    const int g = lane >> 2;
    const int qu = (lane & 3) * 2;
    const int b = blockIdx.z, hh = blockIdx.y;
    const int q0 = blockIdx.x * 256;
    const int bh = b * NH + hh;

    const __half* qgl = g_q16 + ((size_t)bh * NPIX + q0 + wid * 32) * DH;
    const __half* kgl = g_k16 + (size_t)bh * NPIX * DH;
    const __half* vgl = g_v16 + (size_t)bh * DH * NPIX;

    const float kmax = sqrtf(__uint_as_float(g_kmax[bh]));
    uint32_t Bp[2][2];   // packed half2(B,B) per (mi, h2)
#pragma unroll
    for (int mi = 0; mi < 2; mi++)
#pragma unroll
        for (int h2 = 0; h2 < 2; h2++) {
            float Bv = g_qb[(size_t)bh * NPIX + q0 + wid * 32 +
                            mi * 16 + g + h2 * 8] * kmax;
            Bp[mi][h2] = pack_f16x2(Bv, Bv);
        }

    uint32_t qa[2][2][4];
#pragma unroll
    for (int mi = 0; mi < 2; mi++)
#pragma unroll
        for (int kk = 0; kk < 2; kk++) {
            int r0 = mi * 16 + g;
            int c0 = kk * 16 + qu;
            qa[mi][kk][0] = *(const uint32_t*)(qgl + (size_t)r0 * DH + c0);
            qa[mi][kk][1] = *(const uint32_t*)(qgl + (size_t)(r0 + 8) * DH + c0);
            qa[mi][kk][2] = *(const uint32_t*)(qgl + (size_t)r0 * DH + c0 + 8);
            qa[mi][kk][3] = *(const uint32_t*)(qgl + (size_t)(r0 + 8) * DH + c0 + 8);
        }

    float o[2][4][4];
#pragma unroll
    for (int mi = 0; mi < 2; mi++)
#pragma unroll
        for (int ci = 0; ci < 4; ci++)
#pragma unroll
            for (int r = 0; r < 4; r++) o[mi][ci][r] = 0.f;
    float lrun[2][2] = {{0.f, 0.f}, {0.f, 0.f}};

    const int krow = tid >> 2, kpart = tid & 3;
    const int vrow = tid >> 3, vpart = tid & 7;

    const uint32_t ks_base = (uint32_t)__cvta_generic_to_shared(&Ks[0][0][0]);
    const uint32_t vs_base = (uint32_t)__cvta_generic_to_shared(&Vs[0][0][0]);
    const uint32_t koff = ((lane & 7) * 40 + (lane >> 3) * 8) * 2;
    const uint32_t voff = ((((lane >> 4) & 1) * 8 + (lane & 7)) * 72 +
                           ((lane >> 3) & 1) * 8) * 2;
    const uint32_t kst = (uint32_t)(krow * 40 + kpart * 8) * 2;
    const uint32_t vst = (uint32_t)(vrow * 72 + vpart * 8) * 2;
    const __half* kld = kgl + (size_t)krow * DH + kpart * 8;
    const __half* vld = vgl + (size_t)vrow * NPIX + vpart * 8;

#pragma unroll
    for (int s = 0; s < 3; s++) {
        cpasync16(ks_base + s * KBUF + kst, kld + (size_t)(s * 64) * DH);
        cpasync16(vs_base + s * VBUF + vst, vld + s * 64);
        CP_COMMIT();
    }

    for (int i = 0; i < NPIX / 64; i++) {
        asm volatile("cp.async.wait_group 2;" ::: "memory");
        __syncthreads();

        const int st = i & 3;
        const uint32_t kb = ks_base + st * KBUF + koff;
        const uint32_t vb_base = vs_base + st * VBUF + voff;

        // ---- S = Q K^T; p = exp2(pack(s) - Bp) (fp16 sub; B-error cancels) --
        uint32_t p16[2][8][2];
#pragma unroll
        for (int nj = 0; nj < 8; nj++) {
            uint32_t b00, b01, b10, b11;
            ldmx4(b00, b01, b10, b11, kb + nj * (8 * 40 * 2));
            uint32_t bf0[2] = {b00, b01};
            uint32_t bf1[2] = {b10, b11};
#pragma unroll
            for (int mi = 0; mi < 2; mi++) {
                float sacc[4] = {0.f, 0.f, 0.f, 0.f};
                mma16816h(sacc, qa[mi][0], bf0);
                mma16816h(sacc, qa[mi][1], bf1);
                p16[mi][nj][0] = hex2(hsub2(pack_f16x2(sacc[0], sacc[1]),
                                            Bp[mi][0]));
                p16[mi][nj][1] = hex2(hsub2(pack_f16x2(sacc[2], sacc[3]),
                                            Bp[mi][1]));
            }
        }

        // ---- O += P V (tensor path first) ----
#pragma unroll
        for (int kt = 0; kt < 4; kt++) {
            uint32_t v00, v01, v10, v11, v20, v21, v30, v31;
            ldmx4(v00, v01, v10, v11, vb_base + kt * 32);
            ldmx4(v20, v21, v30, v31, vb_base + kt * 32 + (16 * 72 * 2));
            uint32_t vb0[2] = {v00, v01};
            uint32_t vb1[2] = {v10, v11};
            uint32_t vb2[2] = {v20, v21};
            uint32_t vb3[2] = {v30, v31};
#pragma unroll
            for (int mi = 0; mi < 2; mi++) {
                uint32_t ph[4] = {p16[mi][2 * kt][0], p16[mi][2 * kt][1],
                                  p16[mi][2 * kt + 1][0], p16[mi][2 * kt + 1][1]};
                mma16816h(o[mi][0], ph, vb0);
                mma16816h(o[mi][1], ph, vb1);
                mma16816h(o[mi][2], ph, vb2);
                mma16816h(o[mi][3], ph, vb3);
            }
        }

        // ---- row sums (off the critical tensor path) ----
#pragma unroll
        for (int mi = 0; mi < 2; mi++)
#pragma unroll
            for (int h2 = 0; h2 < 2; h2++) {
                uint32_t t = hadd2(
                    hadd2(hadd2(p16[mi][0][h2], p16[mi][1][h2]),
                          hadd2(p16[mi][2][h2], p16[mi][3][h2])),
                    hadd2(hadd2(p16[mi][4][h2], p16[mi][5][h2]),
                          hadd2(p16[mi][6][h2], p16[mi][7][h2])));
                float2 f = __half22float2(*(__half2*)&t);
                lrun[mi][h2] += f.x + f.y;
            }

        if (i + 3 < NPIX / 64) {
            const int nst = (i + 3) & 3;
            cpasync16(ks_base + nst * KBUF + kst,
                      kld + (size_t)((i + 3) * 64) * DH);
            cpasync16(vs_base + nst * VBUF + vst, vld + (i + 3) * 64);
        }
        CP_COMMIT();
    }

    // ---- final row-sum reduce, normalize + store ----
#pragma unroll
    for (int mi = 0; mi < 2; mi++)
#pragma unroll
        for (int h2 = 0; h2 < 2; h2++) {
            float l = lrun[mi][h2];
            l += __shfl_xor_sync(0xffffffffu, l, 1);
            l += __shfl_xor_sync(0xffffffffu, l, 2);
            float invl = 1.0f / l;
            int qrow = q0 + wid * 32 + mi * 16 + g + h2 * 8;
            __half* od = g_at + ((size_t)b * NPIX + qrow) * CC + hh * DH;
#pragma unroll
            for (int ci = 0; ci < 4; ci++) {
                *(__half2*)(od + ci * 8 + qu) =
                    __floats2half2_rn(o[mi][ci][h2 * 2] * invl,
                                      o[mi][ci][h2 * 2 + 1] * invl);
            }
        }
}

// ---------------------------------------------------------------------------
extern "C" void kernel_launch(void* const* d_in, const int* in_sizes, int n_in,
                              void* d_out, int out_size) {
    const float* x      = (const float*)d_in[0];
    const float* norm_w = (const float*)d_in[1];
    const float* norm_b = (const float*)d_in[2];
    const float* qkv_w  = (const float*)d_in[3];
    const float* qkv_b  = (const float*)d_in[4];
    const float* proj_w = (const float*)d_in[5];
    const float* proj_b = (const float*)d_in[6];
    float* out = (float*)d_out;

    __half *g_wp_p, *g_at_p;
    cudaGetSymbolAddress((void**)&g_wp_p, g_wp);
    cudaGetSymbolAddress((void**)&g_at_p, g_at);

    // K0: weight conversion + kmax reset
    wconv_kernel<<<256, 256>>>(qkv_w, proj_w);

    // K1: norm -> fp16 [b][n][c]
    norm_kernel<<<(BB * NPIX) / 64, 256>>>(x, norm_w, norm_b);

    // K2: qkv GEMM + fused attention layouts + bound stats
    gemmqkv_kernel<<<dim3(NPIX / 128, 384 / 64, BB), 256>>>(qkv_b);

    // K3: attention -> fp16 [b][n][c]   (4th launch: ncu profiles this)
    attn_mma_kernel<<<dim3(NPIX / 256, NH, BB), 256>>>();

    // K4: proj + bias + residual -> d_out
    gemm16_kernel<<<dim3(NPIX / 128, CC / 64, BB), 256>>>(
        g_wp_p, proj_b, g_at_p, out, x, CC);
}

// round 16
// speedup vs baseline: 1.0289x; 1.0289x over previous
#include <cuda_runtime.h>
#include <cuda_fp16.h>
#include <math.h>
#include <stdint.h>

#define BB 4
#define CC 128
#define NPIX 4096
#define NH 4
#define DH 32
#define EPSF 1e-6f
// (1/sqrt(32)) * log2(e)
#define SCALE2 0.25503486f

// Scratch (device globals)
__device__ __half g_ht[(size_t)BB * NPIX * CC];        // normed h fp16 [b][n][c]
__device__ __half g_wq[384 * 128];                     // qkv_w plain fp16
__device__ __half g_wp[128 * 128];                     // proj_w plain fp16
__device__ __half g_q16[(size_t)BB * NH * NPIX * DH];  // [bh][n][c], scaled
__device__ __half g_k16[(size_t)BB * NH * NPIX * DH];  // [bh][n][c]
__device__ __half g_v16[(size_t)BB * NH * DH * NPIX];  // [bh][c][n]
__device__ __half g_at[(size_t)BB * NPIX * CC];        // attn out fp16 [b][n][c]
__device__ float  g_qb[BB * NH * NPIX];                // |q_n| per row
__device__ unsigned g_kmax[BB * NH];                   // bits of max |k|^2

// ---------------------------------------------------------------------------
// helpers
// ---------------------------------------------------------------------------
__device__ __forceinline__ uint32_t hex2(uint32_t a) {
    uint32_t d;
    asm("ex2.approx.f16x2 %0, %1;" : "=r"(d) : "r"(a));
    return d;
}

__device__ __forceinline__ uint32_t hadd2(uint32_t a, uint32_t b) {
    uint32_t d;
    asm("add.f16x2 %0, %1, %2;" : "=r"(d) : "r"(a), "r"(b));
    return d;
}

__device__ __forceinline__ void mma16816h(float* d, const uint32_t* a,
                                          const uint32_t* b) {
    asm volatile(
        "mma.sync.aligned.m16n8k16.row.col.f32.f16.f16.f32 "
        "{%0,%1,%2,%3},{%4,%5,%6,%7},{%8,%9},{%0,%1,%2,%3};"
        : "+f"(d[0]), "+f"(d[1]), "+f"(d[2]), "+f"(d[3])
        : "r"(a[0]), "r"(a[1]), "r"(a[2]), "r"(a[3]), "r"(b[0]), "r"(b[1]));
}

__device__ __forceinline__ void ldmx4(uint32_t& r0, uint32_t& r1, uint32_t& r2,
                                      uint32_t& r3, uint32_t addr) {
    asm volatile(
        "ldmatrix.sync.aligned.m8n8.x4.shared.b16 {%0,%1,%2,%3}, [%4];"
        : "=r"(r0), "=r"(r1), "=r"(r2), "=r"(r3) : "r"(addr));
}

__device__ __forceinline__ uint32_t pack_f16x2(float a, float b) {
    uint32_t r;
    asm("cvt.rn.f16x2.f32 %0, %1, %2;" : "=r"(r) : "f"(b), "f"(a));
    return r;
}

__device__ __forceinline__ void cpasync16(uint32_t s, const void* g) {
    asm volatile("cp.async.cg.shared.global [%0], [%1], 16;"
                 :: "r"(s), "l"(g) : "memory");
}
#define CP_COMMIT() asm volatile("cp.async.commit_group;" ::: "memory")

// ---------------------------------------------------------------------------
// K0: weight conversion (both plain fp16) + g_kmax reset
// ---------------------------------------------------------------------------
__global__ void wconv_kernel(const float* __restrict__ qkv_w,
                             const float* __restrict__ proj_w) {
    int t = blockIdx.x * 256 + threadIdx.x;   // 0 .. 65535
    if (t < BB * NH) g_kmax[t] = 0u;
    if (t < 384 * 128) {
        g_wq[t] = __float2half_rn(qkv_w[t]);
    } else {
        int idx = t - 384 * 128;
        g_wp[idx] = __float2half_rn(proj_w[idx]);
    }
}

// ---------------------------------------------------------------------------
// K1: LayerNorm, 4 threads/pixel -> fp16 [b][n][c]. 256 CTAs.
// ---------------------------------------------------------------------------
__global__ void __launch_bounds__(256) norm_kernel(
    const float* __restrict__ x, const float* __restrict__ w,
    const float* __restrict__ bias) {
    __shared__ float sred[2][4][64];
    const int tid = threadIdx.x;
    const int n_loc = tid & 63;
    const int cg = tid >> 6;
    const int pix = blockIdx.x * 64 + n_loc;
    const int b = pix >> 12, n = pix & (NPIX - 1);
    const float* xp = x + (size_t)b * CC * NPIX + n;

    float vals[32];
    float s = 0.f, s2 = 0.f;
#pragma unroll
    for (int i = 0; i < 32; i++) {
        float v = xp[(size_t)(cg * 32 + i) * NPIX];
        vals[i] = v;
        s += v;
        s2 = fmaf(v, v, s2);
    }
    sred[0][cg][n_loc] = s;
    sred[1][cg][n_loc] = s2;
    __syncthreads();
    s  = sred[0][0][n_loc] + sred[0][1][n_loc] + sred[0][2][n_loc] + sred[0][3][n_loc];
    s2 = sred[1][0][n_loc] + sred[1][1][n_loc] + sred[1][2][n_loc] + sred[1][3][n_loc];
    float mean = s * (1.0f / CC);
    float var  = s2 * (1.0f / CC) - mean * mean;
    float inv  = rsqrtf(var + EPSF);

    __half* hp = g_ht + ((size_t)b * NPIX + n) * CC + cg * 32;
#pragma unroll
    for (int i = 0; i < 32; i += 2) {
        int c = cg * 32 + i;
        float v0 = (vals[i] - mean) * inv * w[c] + bias[c];
        float v1 = (vals[i + 1] - mean) * inv * w[c + 1] + bias[c + 1];
        *(__half2*)(hp + i) = __floats2half2_rn(v0, v1);
    }
}

// ---------------------------------------------------------------------------
// K2: qkv GEMM (plain fp16 weights) + fused layouts + stats.
// ---------------------------------------------------------------------------
__global__ void __launch_bounds__(256) gemmqkv_kernel(
    const float* __restrict__ bias) {
    __shared__ __align__(16) __half Hs[128][136];
    __shared__ float red[8];

    const int tid = threadIdx.x, lane = tid & 31, wid = tid >> 5;
    const int g = lane >> 2, qu = (lane & 3) * 2;
    const int b = blockIdx.z, o0 = blockIdx.y * 64, n0 = blockIdx.x * 128;
    const int os = wid & 3, ns = wid >> 2;

    {
        const __half* hsrc = g_ht + ((size_t)b * NPIX + n0) * CC;
        int row = tid >> 1, part = tid & 1;
#pragma unroll
        for (int j = 0; j < 8; j++)
            *(uint4*)&Hs[row][part * 64 + j * 8] =
                *(const uint4*)(hsrc + (size_t)row * CC + part * 64 + j * 8);
    }
    __syncthreads();

    float acc[8][4];
#pragma unroll
    for (int nj = 0; nj < 8; nj++)
#pragma unroll
        for (int r = 0; r < 4; r++) acc[nj][r] = 0.f;

    const __half* w0 = g_wq + (size_t)(o0 + os * 16 + g) * 128;
    const __half* w8 = w0 + 8 * 128;

#pragma unroll
    for (int kk = 0; kk < 8; kk++) {
        int c0 = kk * 16 + qu;
        uint32_t ah[4];
        ah[0] = *(const uint32_t*)(w0 + c0);
        ah[1] = *(const uint32_t*)(w8 + c0);
        ah[2] = *(const uint32_t*)(w0 + c0 + 8);
        ah[3] = *(const uint32_t*)(w8 + c0 + 8);
#pragma unroll
        for (int nj = 0; nj < 8; nj++) {
            uint32_t bf[2];
            const __half* hrow = &Hs[ns * 64 + nj * 8 + g][0];
            bf[0] = *(const uint32_t*)(hrow + c0);
            bf[1] = *(const uint32_t*)(hrow + c0 + 8);
            mma16816h(acc[nj], ah, bf);
        }
    }

    const int orow = o0 + os * 16 + g;
    const float b0 = bias[orow], b8 = bias[orow + 8];

    if (o0 >= 256) {
        int h = (orow - 256) >> 5, c = orow & 31;
        __half* v0p = g_v16 + ((size_t)(b * NH + h) * DH + c) * NPIX + n0;
        __half* v8p = v0p + 8 * NPIX;
#pragma unroll
        for (int nj = 0; nj < 8; nj++) {
            int n = ns * 64 + nj * 8 + qu;
            *(__half2*)(v0p + n) = __floats2half2_rn(acc[nj][0] + b0, acc[nj][1] + b0);
            *(__half2*)(v8p + n) = __floats2half2_rn(acc[nj][2] + b8, acc[nj][3] + b8);
        }
    } else {
        const bool isQ = (o0 < 128);
        const float sc = isQ ? SCALE2 : 1.0f;
        __syncthreads();
        int lo = os * 16 + g;
#pragma unroll
        for (int nj = 0; nj < 8; nj++) {
            int nn = ns * 64 + nj * 8 + qu;
            *(__half2*)&Hs[lo][nn] =
                __floats2half2_rn((acc[nj][0] + b0) * sc, (acc[nj][1] + b0) * sc);
            *(__half2*)&Hs[lo + 8][nn] =
                __floats2half2_rn((acc[nj][2] + b8) * sc, (acc[nj][3] + b8) * sc);
        }
        __syncthreads();
        int n_loc = tid & 127;
        int hseg = tid >> 7;
        int oBase = (isQ ? o0 : o0 - 128) + hseg * 32;
        int head = oBase >> 5;
        int bh = b * NH + head;
        __half* dst = (isQ ? g_q16 : g_k16) +
                      ((size_t)bh * NPIX + n0 + n_loc) * DH;
        __half tmp[32];
        float nrm2 = 0.f;
#pragma unroll
        for (int c = 0; c < 32; c++) {
            tmp[c] = Hs[hseg * 32 + c][n_loc];
            float f = __half2float(tmp[c]);
            nrm2 = fmaf(f, f, nrm2);
        }
#pragma unroll
        for (int j = 0; j < 4; j++)
            *(uint4*)(dst + j * 8) = *(uint4*)(tmp + j * 8);

        if (isQ) {
            g_qb[(size_t)bh * NPIX + n0 + n_loc] = sqrtf(nrm2);
        } else {
#pragma unroll
            for (int off = 16; off > 0; off >>= 1)
                nrm2 = fmaxf(nrm2, __shfl_xor_sync(0xffffffffu, nrm2, off));
            if (lane == 0) red[wid] = nrm2;
            __syncthreads();
            if ((tid & 127) == 0) {
                float m = fmaxf(fmaxf(red[hseg * 4], red[hseg * 4 + 1]),
                                fmaxf(red[hseg * 4 + 2], red[hseg * 4 + 3]));
                atomicMax(&g_kmax[bh], __float_as_uint(m));
            }
        }
    }
}

// ---------------------------------------------------------------------------
// K4: proj GEMM (plain fp16 weights): fp32 out + bias + residual
// ---------------------------------------------------------------------------
__global__ void __launch_bounds__(256) gemm16_kernel(
    const __half* __restrict__ W2, const float* __restrict__ bias,
    const __half* __restrict__ Hin, float* __restrict__ Out,
    const float* __restrict__ resid, int Otot) {
    __shared__ __align__(16) __half Hs[128][136];

    const int tid = threadIdx.x, lane = tid & 31, wid = tid >> 5;
    const int g = lane >> 2, qu = (lane & 3) * 2;
    const int b = blockIdx.z, o0 = blockIdx.y * 64, n0 = blockIdx.x * 128;
    const int os = wid & 3, ns = wid >> 2;

    {
        const __half* hsrc = Hin + ((size_t)b * NPIX + n0) * CC;
        int row = tid >> 1, part = tid & 1;
#pragma unroll
        for (int j = 0; j < 8; j++)
            *(uint4*)&Hs[row][part * 64 + j * 8] =
                *(const uint4*)(hsrc + (size_t)row * CC + part * 64 + j * 8);
    }
    __syncthreads();

    float acc[8][4];
#pragma unroll
    for (int nj = 0; nj < 8; nj++)
#pragma unroll
        for (int r = 0; r < 4; r++) acc[nj][r] = 0.f;

    const __half* w0 = W2 + (size_t)(o0 + os * 16 + g) * 128;
    const __half* w8 = w0 + 8 * 128;

#pragma unroll
    for (int kk = 0; kk < 8; kk++) {
        int c0 = kk * 16 + qu;
        uint32_t ah[4];
        ah[0] = *(const uint32_t*)(w0 + c0);
        ah[1] = *(const uint32_t*)(w8 + c0);
        ah[2] = *(const uint32_t*)(w0 + c0 + 8);
        ah[3] = *(const uint32_t*)(w8 + c0 + 8);
#pragma unroll
        for (int nj = 0; nj < 8; nj++) {
            uint32_t bf[2];
            const __half* hrow = &Hs[ns * 64 + nj * 8 + g][0];
            bf[0] = *(const uint32_t*)(hrow + c0);
            bf[1] = *(const uint32_t*)(hrow + c0 + 8);
            mma16816h(acc[nj], ah, bf);
        }
    }

    const int orow = o0 + os * 16 + g;
    const float b0 = bias[orow], b8 = bias[orow + 8];
#pragma unroll
    for (int nj = 0; nj < 8; nj++) {
        int n = n0 + ns * 64 + nj * 8 + qu;
        float2 v0 = make_float2(acc[nj][0] + b0, acc[nj][1] + b0);
        float2 v1 = make_float2(acc[nj][2] + b8, acc[nj][3] + b8);
        float2 r0 = *(const float2*)(resid + ((size_t)b * Otot + orow) * NPIX + n);
        float2 r1 = *(const float2*)(resid + ((size_t)b * Otot + orow + 8) * NPIX + n);
        v0.x += r0.x; v0.y += r0.y;
        v1.x += r1.x; v1.y += r1.y;
        *(float2*)(Out + ((size_t)b * Otot + orow) * NPIX + n) = v0;
        *(float2*)(Out + ((size_t)b * Otot + orow + 8) * NPIX + n) = v1;
    }
}

// ---------------------------------------------------------------------------
// K3: flash attention, softmax-bound, 4-stage cp.async pipeline.
// (round-14 body: QK -> sums -> PV, fp32 subtract + hex2)
// CTA = 256 thr (8 warps), warp = 32 q rows (2 mi tiles) -> 256 q per CTA.
// ---------------------------------------------------------------------------
#define KBUF (64 * 40 * 2)
#define VBUF (32 * 72 * 2)
__global__ void __launch_bounds__(256, 2) attn_mma_kernel() {
    __shared__ __align__(16) __half Ks[4][64][40];
    __shared__ __align__(16) __half Vs[4][32][72];

    const int tid = threadIdx.x;
    const int lane = tid & 31;
    const int wid = tid >> 5;
    const int g = lane >> 2;
    const int qu = (lane & 3) * 2;
    const int b = blockIdx.z, hh = blockIdx.y;
    const int q0 = blockIdx.x * 256;
    const int bh = b * NH + hh;

    const __half* qgl = g_q16 + ((size_t)bh * NPIX + q0 + wid * 32) * DH;
    const __half* kgl = g_k16 + (size_t)bh * NPIX * DH;
    const __half* vgl = g_v16 + (size_t)bh * DH * NPIX;

    const float kmax = sqrtf(__uint_as_float(g_kmax[bh]));
    float B[2][2];
#pragma unroll
    for (int mi = 0; mi < 2; mi++)
#pragma unroll
        for (int h2 = 0; h2 < 2; h2++)
            B[mi][h2] = g_qb[(size_t)bh * NPIX + q0 + wid * 32 +
                             mi * 16 + g + h2 * 8] * kmax;

    uint32_t qa[2][2][4];
#pragma unroll
    for (int mi = 0; mi < 2; mi++)
#pragma unroll
        for (int kk = 0; kk < 2; kk++) {
            int r0 = mi * 16 + g;
            int c0 = kk * 16 + qu;
            qa[mi][kk][0] = *(const uint32_t*)(qgl + (size_t)r0 * DH + c0);
            qa[mi][kk][1] = *(const uint32_t*)(qgl + (size_t)(r0 + 8) * DH + c0);
            qa[mi][kk][2] = *(const uint32_t*)(qgl + (size_t)r0 * DH + c0 + 8);
            qa[mi][kk][3] = *(const uint32_t*)(qgl + (size_t)(r0 + 8) * DH + c0 + 8);
        }

    float o[2][4][4];
#pragma unroll
    for (int mi = 0; mi < 2; mi++)
#pragma unroll
        for (int ci = 0; ci < 4; ci++)
#pragma unroll
            for (int r = 0; r < 4; r++) o[mi][ci][r] = 0.f;
    float lrun[2][2] = {{0.f, 0.f}, {0.f, 0.f}};

    const int krow = tid >> 2, kpart = tid & 3;
    const int vrow = tid >> 3, vpart = tid & 7;

    const uint32_t ks_base = (uint32_t)__cvta_generic_to_shared(&Ks[0][0][0]);
    const uint32_t vs_base = (uint32_t)__cvta_generic_to_shared(&Vs[0][0][0]);
    const uint32_t koff = ((lane & 7) * 40 + (lane >> 3) * 8) * 2;
    const uint32_t voff = ((((lane >> 4) & 1) * 8 + (lane & 7)) * 72 +
                           ((lane >> 3) & 1) * 8) * 2;
    const uint32_t kst = (uint32_t)(krow * 40 + kpart * 8) * 2;
    const uint32_t vst = (uint32_t)(vrow * 72 + vpart * 8) * 2;
    const __half* kld = kgl + (size_t)krow * DH + kpart * 8;
    const __half* vld = vgl + (size_t)vrow * NPIX + vpart * 8;

    // preload chunks 0..2
#pragma unroll
    for (int s = 0; s < 3; s++) {
        cpasync16(ks_base + s * KBUF + kst, kld + (size_t)(s * 64) * DH);
        cpasync16(vs_base + s * VBUF + vst, vld + s * 64);
        CP_COMMIT();
    }

    for (int i = 0; i < NPIX / 64; i++) {
        asm volatile("cp.async.wait_group 2;" ::: "memory");
        __syncthreads();

        const int st = i & 3;
        const uint32_t kb = ks_base + st * KBUF + koff;
        const uint32_t vb_base = vs_base + st * VBUF + voff;

        // ---- S = Q K^T (k=32); K fragments shared across both mi tiles ----
        uint32_t p16[2][8][2];
#pragma unroll
        for (int nj = 0; nj < 8; nj++) {
            uint32_t b00, b01, b10, b11;
            ldmx4(b00, b01, b10, b11, kb + nj * (8 * 40 * 2));
            uint32_t bf0[2] = {b00, b01};
            uint32_t bf1[2] = {b10, b11};
#pragma unroll
            for (int mi = 0; mi < 2; mi++) {
                float sacc[4] = {0.f, 0.f, 0.f, 0.f};
                mma16816h(sacc, qa[mi][0], bf0);
                mma16816h(sacc, qa[mi][1], bf1);
                p16[mi][nj][0] = hex2(pack_f16x2(sacc[0] - B[mi][0],
                                                 sacc[1] - B[mi][0]));
                p16[mi][nj][1] = hex2(pack_f16x2(sacc[2] - B[mi][1],
                                                 sacc[3] - B[mi][1]));
            }
        }

        // ---- per-lane partial row sums ----
#pragma unroll
        for (int mi = 0; mi < 2; mi++)
#pragma unroll
            for (int h2 = 0; h2 < 2; h2++) {
                uint32_t t = hadd2(
                    hadd2(hadd2(p16[mi][0][h2], p16[mi][1][h2]),
                          hadd2(p16[mi][2][h2], p16[mi][3][h2])),
                    hadd2(hadd2(p16[mi][4][h2], p16[mi][5][h2]),
                          hadd2(p16[mi][6][h2], p16[mi][7][h2])));
                float2 f = __half22float2(*(__half2*)&t);
                lrun[mi][h2] += f.x + f.y;
            }

        // ---- O += P V; V fragments shared across both mi tiles ----
#pragma unroll
        for (int kt = 0; kt < 4; kt++) {
            uint32_t v00, v01, v10, v11, v20, v21, v30, v31;
            ldmx4(v00, v01, v10, v11, vb_base + kt * 32);
            ldmx4(v20, v21, v30, v31, vb_base + kt * 32 + (16 * 72 * 2));
            uint32_t vb0[2] = {v00, v01};
            uint32_t vb1[2] = {v10, v11};
            uint32_t vb2[2] = {v20, v21};
            uint32_t vb3[2] = {v30, v31};
#pragma unroll
            for (int mi = 0; mi < 2; mi++) {
                uint32_t ph[4] = {p16[mi][2 * kt][0], p16[mi][2 * kt][1],
                                  p16[mi][2 * kt + 1][0], p16[mi][2 * kt + 1][1]};
                mma16816h(o[mi][0], ph, vb0);
                mma16816h(o[mi][1], ph, vb1);
                mma16816h(o[mi][2], ph, vb2);
                mma16816h(o[mi][3], ph, vb3);
            }
        }

        if (i + 3 < NPIX / 64) {
            const int nst = (i + 3) & 3;
            cpasync16(ks_base + nst * KBUF + kst,
                      kld + (size_t)((i + 3) * 64) * DH);
            cpasync16(vs_base + nst * VBUF + vst, vld + (i + 3) * 64);
        }
        CP_COMMIT();
    }

    // ---- final row-sum reduce, normalize + store ----
#pragma unroll
    for (int mi = 0; mi < 2; mi++)
#pragma unroll
        for (int h2 = 0; h2 < 2; h2++) {
            float l = lrun[mi][h2];
            l += __shfl_xor_sync(0xffffffffu, l, 1);
            l += __shfl_xor_sync(0xffffffffu, l, 2);
            float invl = 1.0f / l;
            int qrow = q0 + wid * 32 + mi * 16 + g + h2 * 8;
            __half* od = g_at + ((size_t)b * NPIX + qrow) * CC + hh * DH;
#pragma unroll
            for (int ci = 0; ci < 4; ci++) {
                *(__half2*)(od + ci * 8 + qu) =
                    __floats2half2_rn(o[mi][ci][h2 * 2] * invl,
                                      o[mi][ci][h2 * 2 + 1] * invl);
            }
        }
}

// ---------------------------------------------------------------------------
extern "C" void kernel_launch(void* const* d_in, const int* in_sizes, int n_in,
                              void* d_out, int out_size) {
    const float* x      = (const float*)d_in[0];
    const float* norm_w = (const float*)d_in[1];
    const float* norm_b = (const float*)d_in[2];
    const float* qkv_w  = (const float*)d_in[3];
    const float* qkv_b  = (const float*)d_in[4];
    const float* proj_w = (const float*)d_in[5];
    const float* proj_b = (const float*)d_in[6];
    float* out = (float*)d_out;

    __half *g_wp_p, *g_at_p;
    cudaGetSymbolAddress((void**)&g_wp_p, g_wp);
    cudaGetSymbolAddress((void**)&g_at_p, g_at);

    // K0: weight conversion + kmax reset
    wconv_kernel<<<256, 256>>>(qkv_w, proj_w);

    // K1: norm -> fp16 [b][n][c]
    norm_kernel<<<(BB * NPIX) / 64, 256>>>(x, norm_w, norm_b);

    // K2: qkv GEMM + fused attention layouts + bound stats
    gemmqkv_kernel<<<dim3(NPIX / 128, 384 / 64, BB), 256>>>(qkv_b);

    // K3: attention -> fp16 [b][n][c]   (4th launch: ncu profiles this)
    attn_mma_kernel<<<dim3(NPIX / 256, NH, BB), 256>>>();

    // K4: proj + bias + residual -> d_out
    gemm16_kernel<<<dim3(NPIX / 128, CC / 64, BB), 256>>>(
        g_wp_p, proj_b, g_at_p, out, x, CC);
}